// round 14
// baseline (speedup 1.0000x reference)
#include <cuda_runtime.h>
#include <cuda_fp16.h>
#include <cstddef>

#define NW    100000
#define VD    128
#define BATCH 16384
#define KNUM  26
#define NQUAD 7    // k-quads; warp wid owns q = wid + 4*i, i = 0..1
#define NQW   2

#define GB     512                 // gather blocks (256 thr, 8 warps x 4 b)
#define TBX    (NW / 32)           // 3125
#define TBY    (VD / 32)           // 4
#define NBLK   (GB + TBX * TBY)    // fused prep grid

// Scratch (static device globals; no allocation):
//   g_OTh: 25.6 MB fp16 transposed O, OTh[word][v]
//   g_dgh: 4 MB   fp16 gathered doc vectors, dgh[b][v]
__device__ __half g_OTh[(size_t)NW * VD];
__device__ __half g_dgh[(size_t)BATCH * VD];

// ---------------------------------------------------------------------------
// Kernel A (fused): blocks [0, GB) gather dgh[b] = fp16(D[doc_ids[b]]) with
// 4 b's per warp (MLP=4); blocks [GB, ...) transpose O [VD, NW] f32 ->
// OTh [NW, VD] fp16, tiled 32x32 via smem. Gather blocks lead the grid so
// their latency overlaps the DRAM-bound transpose.
// ---------------------------------------------------------------------------
__global__ __launch_bounds__(256)
void prep_kernel(const int* __restrict__ doc_ids,
                 const float* __restrict__ D,
                 const float* __restrict__ O) {
    const int t = threadIdx.x;

    if (blockIdx.x < GB) {
        // ---- gather partition ----
        const int warp = t >> 5;
        const int lane = t & 31;
        const int b0   = (blockIdx.x * 8 + warp) * 4;

        int doc[4];
#pragma unroll
        for (int i = 0; i < 4; i++) doc[i] = __ldg(&doc_ids[b0 + i]);

        float4 v[4];
#pragma unroll
        for (int i = 0; i < 4; i++) {
            v[i] = __ldg(reinterpret_cast<const float4*>(
                             D + (size_t)doc[i] * VD) + lane);
        }
#pragma unroll
        for (int i = 0; i < 4; i++) {
            const __half2 p0 = __floats2half2_rn(v[i].x, v[i].y);
            const __half2 p1 = __floats2half2_rn(v[i].z, v[i].w);
            uint2 o;
            o.x = *reinterpret_cast<const unsigned*>(&p0);
            o.y = *reinterpret_cast<const unsigned*>(&p1);
            *reinterpret_cast<uint2*>(
                g_dgh + (size_t)(b0 + i) * VD + 4 * lane) = o;
        }
        return;
    }

    // ---- transpose partition ----
    const int idx = blockIdx.x - GB;
    const int w0  = (idx % TBX) * 32;
    const int v0  = (idx / TBX) * 32;

    __shared__ float tile[32][33];

    {   // read: thread (ty = v_local, tx = w-float4-chunk), coalesced along w
        const int ty = t >> 3;
        const int tx = t & 7;
        const float4 f = __ldg(reinterpret_cast<const float4*>(
                                   O + (size_t)(v0 + ty) * NW + w0) + tx);
        tile[ty][4 * tx + 0] = f.x;
        tile[ty][4 * tx + 1] = f.y;
        tile[ty][4 * tx + 2] = f.z;
        tile[ty][4 * tx + 3] = f.w;
    }
    __syncthreads();

    {   // write: thread (wl = w_local, vc = v-quad) -> 4 halves (8B)
        const int wl = t >> 3;
        const int vc = t & 7;
        const __half2 p0 = __floats2half2_rn(tile[4 * vc + 0][wl],
                                             tile[4 * vc + 1][wl]);
        const __half2 p1 = __floats2half2_rn(tile[4 * vc + 2][wl],
                                             tile[4 * vc + 3][wl]);
        uint2 o;
        o.x = *reinterpret_cast<const unsigned*>(&p0);
        o.y = *reinterpret_cast<const unsigned*>(&p1);
        *reinterpret_cast<uint2*>(
            g_OTh + (size_t)(w0 + wl) * VD + v0 + 4 * vc) = o;
    }
}

// ---------------------------------------------------------------------------
// Kernel B: score. One block (128 thr = 4 warps) per b (R11 config — the
// 2-b/256-thr variant regressed). Quarter-warp layout: quar = lane>>3 picks
// one of 4 k's handled at once; sub8 = lane&7 covers 16 v-elements (2 x
// uint4 = 8 half2). Warp wid owns quads q = wid + 4i, i<2 (quad 6 partial:
// clamp tnids index, predicate store). Reduce = 3 shuffles per 4 scores.
// ---------------------------------------------------------------------------
__global__ __launch_bounds__(VD)
void score_kernel(const int* __restrict__ tnids,
                  float* __restrict__ out) {
    const int b    = blockIdx.x;
    const int t    = threadIdx.x;
    const int lane = t & 31;
    const int wid  = t >> 5;
    const int quar = lane >> 3;   // 0..3 : k = 4q + quar
    const int sub8 = lane & 7;    // v = 16*sub8 .. 16*sub8+15

    // doc vector chunk (fp16, 16 halves). Same 256B broadcast across quads.
    const uint4 da = __ldg(reinterpret_cast<const uint4*>(
                               g_dgh + (size_t)b * VD + 16 * sub8));
    const uint4 db = __ldg(reinterpret_cast<const uint4*>(
                               g_dgh + (size_t)b * VD + 16 * sub8 + 8));

    // word ids (4 distinct addresses per warp, clamped for quad 6 tail)
    int words[NQW];
#pragma unroll
    for (int i = 0; i < NQW; i++) {
        const int q = wid + 4 * i;
        const int k = 4 * q + quar;
        const int kc = k < KNUM ? k : KNUM - 1;
        words[i] = (q < NQUAD) ? __ldg(&tnids[b * KNUM + kc]) : 0;
    }

    // OT rows, batched (MLP=4): two LDG.128 per slot per lane
    uint4 ra[NQW], rb[NQW];
#pragma unroll
    for (int i = 0; i < NQW; i++) {
        const int q = wid + 4 * i;
        if (q < NQUAD) {
            const __half* row = g_OTh + (size_t)words[i] * VD + 16 * sub8;
            ra[i] = __ldg(reinterpret_cast<const uint4*>(row));
            rb[i] = __ldg(reinterpret_cast<const uint4*>(row + 8));
        }
    }

    const __half2* dah = reinterpret_cast<const __half2*>(&da);
    const __half2* dbh = reinterpret_cast<const __half2*>(&db);

#pragma unroll
    for (int i = 0; i < NQW; i++) {
        const int q = wid + 4 * i;            // warp-uniform
        if (q < NQUAD) {
            const __half2* rah = reinterpret_cast<const __half2*>(&ra[i]);
            const __half2* rbh = reinterpret_cast<const __half2*>(&rb[i]);
            __half2 acc = __hmul2(rah[0], dah[0]);
            acc = __hfma2(rah[1], dah[1], acc);
            acc = __hfma2(rah[2], dah[2], acc);
            acc = __hfma2(rah[3], dah[3], acc);
            __half2 acc2 = __hmul2(rbh[0], dbh[0]);
            acc2 = __hfma2(rbh[1], dbh[1], acc2);
            acc2 = __hfma2(rbh[2], dbh[2], acc2);
            acc2 = __hfma2(rbh[3], dbh[3], acc2);
            acc = __hadd2(acc, acc2);
            const float2 f = __half22float2(acc);
            float s = f.x + f.y;
            s += __shfl_xor_sync(0xffffffffu, s, 4);
            s += __shfl_xor_sync(0xffffffffu, s, 2);
            s += __shfl_xor_sync(0xffffffffu, s, 1);
            const int k = 4 * q + quar;
            if (sub8 == 0 && k < KNUM) out[b * KNUM + k] = s;
        }
    }
}

// ---------------------------------------------------------------------------
// Inputs (metadata order): context_ids[B] i32 (unused), doc_ids[B] i32,
// target_noise_ids[B*K] i32, D[NUM_DOCS*VD] f32, O[VD*NW] f32.
// Output: out[B*K] f32.
// ---------------------------------------------------------------------------
extern "C" void kernel_launch(void* const* d_in, const int* in_sizes, int n_in,
                              void* d_out, int out_size) {
    const int*   doc_ids = (const int*)d_in[1];
    const int*   tnids   = (const int*)d_in[2];
    const float* D       = (const float*)d_in[3];
    const float* O       = (const float*)d_in[4];
    float*       out     = (float*)d_out;

    prep_kernel<<<NBLK, 256>>>(doc_ids, D, O);
    score_kernel<<<BATCH, VD>>>(tnids, out);
}

// round 15
// speedup vs baseline: 1.0580x; 1.0580x over previous
#include <cuda_runtime.h>
#include <cuda_fp16.h>
#include <cstddef>

#define NW    100000
#define VD    128
#define BATCH 16384
#define KNUM  26
#define NPAIR 13   // k-pairs; warp wid owns p = wid + 4*i, i = 0..3
#define NPW   4
#define BPB   8    // batch elements per score block, sequential

#define GB     512                 // gather blocks (256 thr, 8 warps x 4 b)
#define TBX    (NW / 32)           // 3125
#define TBY    (VD / 32)           // 4
#define NBLK   (GB + TBX * TBY)    // fused prep grid

// Scratch (static device globals; no allocation):
//   g_OTh: 25.6 MB fp16 transposed O, OTh[word][v]
//   g_dgh: 4 MB   fp16 gathered doc vectors, dgh[b][v]
__device__ __half g_OTh[(size_t)NW * VD];
__device__ __half g_dgh[(size_t)BATCH * VD];

// ---------------------------------------------------------------------------
// Kernel A (fused): blocks [0, GB) gather dgh[b] = fp16(D[doc_ids[b]]) with
// 4 b's per warp (MLP=4); blocks [GB, ...) transpose O [VD, NW] f32 ->
// OTh [NW, VD] fp16, tiled 32x32 via smem. Gather blocks lead the grid so
// their latency overlaps the DRAM-bound transpose.
// ---------------------------------------------------------------------------
__global__ __launch_bounds__(256)
void prep_kernel(const int* __restrict__ doc_ids,
                 const float* __restrict__ D,
                 const float* __restrict__ O) {
    const int t = threadIdx.x;

    if (blockIdx.x < GB) {
        // ---- gather partition ----
        const int warp = t >> 5;
        const int lane = t & 31;
        const int b0   = (blockIdx.x * 8 + warp) * 4;

        int doc[4];
#pragma unroll
        for (int i = 0; i < 4; i++) doc[i] = __ldg(&doc_ids[b0 + i]);

        float4 v[4];
#pragma unroll
        for (int i = 0; i < 4; i++) {
            v[i] = __ldg(reinterpret_cast<const float4*>(
                             D + (size_t)doc[i] * VD) + lane);
        }
#pragma unroll
        for (int i = 0; i < 4; i++) {
            const __half2 p0 = __floats2half2_rn(v[i].x, v[i].y);
            const __half2 p1 = __floats2half2_rn(v[i].z, v[i].w);
            uint2 o;
            o.x = *reinterpret_cast<const unsigned*>(&p0);
            o.y = *reinterpret_cast<const unsigned*>(&p1);
            *reinterpret_cast<uint2*>(
                g_dgh + (size_t)(b0 + i) * VD + 4 * lane) = o;
        }
        return;
    }

    // ---- transpose partition ----
    const int idx = blockIdx.x - GB;
    const int w0  = (idx % TBX) * 32;
    const int v0  = (idx / TBX) * 32;

    __shared__ float tile[32][33];

    {   // read: thread (ty = v_local, tx = w-float4-chunk), coalesced along w
        const int ty = t >> 3;
        const int tx = t & 7;
        const float4 f = __ldg(reinterpret_cast<const float4*>(
                                   O + (size_t)(v0 + ty) * NW + w0) + tx);
        tile[ty][4 * tx + 0] = f.x;
        tile[ty][4 * tx + 1] = f.y;
        tile[ty][4 * tx + 2] = f.z;
        tile[ty][4 * tx + 3] = f.w;
    }
    __syncthreads();

    {   // write: thread (wl = w_local, vc = v-quad) -> 4 halves (8B)
        const int wl = t >> 3;
        const int vc = t & 7;
        const __half2 p0 = __floats2half2_rn(tile[4 * vc + 0][wl],
                                             tile[4 * vc + 1][wl]);
        const __half2 p1 = __floats2half2_rn(tile[4 * vc + 2][wl],
                                             tile[4 * vc + 3][wl]);
        uint2 o;
        o.x = *reinterpret_cast<const unsigned*>(&p0);
        o.y = *reinterpret_cast<const unsigned*>(&p1);
        *reinterpret_cast<uint2*>(
            g_OTh + (size_t)(w0 + wl) * VD + v0 + 4 * vc) = o;
    }
}

// ---------------------------------------------------------------------------
// Kernel B: score. 2048 blocks x 128 threads; each block processes BPB=8
// consecutive b's SEQUENTIALLY with the proven R11 per-warp body:
// half-warp layout (lanes 0-15: k=2p, lanes 16-31: k=2p+1), lane covers
// 8 v as uint4; warp wid owns pairs p = wid+4i; dot = HMUL2+3xHFMA2;
// 4 shuffles shared by two scores; loads front-batched per b (MLP=4).
// Single wave (oe=14): kills ~6 wave transitions and divides the
// cross-CTA L1tex-queue spread slope by 8 (T_CTA up 8x).
// ---------------------------------------------------------------------------
__global__ __launch_bounds__(VD)
void score_kernel(const int* __restrict__ tnids,
                  float* __restrict__ out) {
    const int t    = threadIdx.x;
    const int lane = t & 31;
    const int wid  = t >> 5;
    const int half = lane >> 4;   // 0: k=2p, 1: k=2p+1
    const int sub  = lane & 15;   // v = 8*sub .. 8*sub+7
    const int b0   = blockIdx.x * BPB;

    for (int bi = 0; bi < BPB; bi++) {
        const int b = b0 + bi;

        // doc vector chunk (fp16, 8 halves)
        const uint4 dbits = __ldg(reinterpret_cast<const uint4*>(
                                      g_dgh + (size_t)b * VD + 8 * sub));
        const __half2 d0 = *reinterpret_cast<const __half2*>(&dbits.x);
        const __half2 d1 = *reinterpret_cast<const __half2*>(&dbits.y);
        const __half2 d2 = *reinterpret_cast<const __half2*>(&dbits.z);
        const __half2 d3 = *reinterpret_cast<const __half2*>(&dbits.w);

        // word ids (2 distinct addresses per warp -> broadcast, batched)
        int words[NPW];
#pragma unroll
        for (int i = 0; i < NPW; i++) {
            const int p = wid + 4 * i;
            words[i] = (p < NPAIR) ? __ldg(&tnids[b * KNUM + 2 * p + half]) : 0;
        }

        // OT rows, batched (MLP=4): one LDG.128 per slot per lane
        uint4 rows[NPW];
#pragma unroll
        for (int i = 0; i < NPW; i++) {
            const int p = wid + 4 * i;
            if (p < NPAIR) {
                rows[i] = __ldg(reinterpret_cast<const uint4*>(
                                    g_OTh + (size_t)words[i] * VD + 8 * sub));
            }
        }

#pragma unroll
        for (int i = 0; i < NPW; i++) {
            const int p = wid + 4 * i;            // warp-uniform
            if (p < NPAIR) {
                const __half2 r0 = *reinterpret_cast<const __half2*>(&rows[i].x);
                const __half2 r1 = *reinterpret_cast<const __half2*>(&rows[i].y);
                const __half2 r2 = *reinterpret_cast<const __half2*>(&rows[i].z);
                const __half2 r3 = *reinterpret_cast<const __half2*>(&rows[i].w);
                __half2 acc = __hmul2(r0, d0);
                acc = __hfma2(r1, d1, acc);
                acc = __hfma2(r2, d2, acc);
                acc = __hfma2(r3, d3, acc);
                const float2 f = __half22float2(acc);
                float s = f.x + f.y;
                s += __shfl_xor_sync(0xffffffffu, s, 8);
                s += __shfl_xor_sync(0xffffffffu, s, 4);
                s += __shfl_xor_sync(0xffffffffu, s, 2);
                s += __shfl_xor_sync(0xffffffffu, s, 1);
                if (sub == 0) out[b * KNUM + 2 * p + half] = s;  // lanes 0,16
            }
        }
    }
}

// ---------------------------------------------------------------------------
// Inputs (metadata order): context_ids[B] i32 (unused), doc_ids[B] i32,
// target_noise_ids[B*K] i32, D[NUM_DOCS*VD] f32, O[VD*NW] f32.
// Output: out[B*K] f32.
// ---------------------------------------------------------------------------
extern "C" void kernel_launch(void* const* d_in, const int* in_sizes, int n_in,
                              void* d_out, int out_size) {
    const int*   doc_ids = (const int*)d_in[1];
    const int*   tnids   = (const int*)d_in[2];
    const float* D       = (const float*)d_in[3];
    const float* O       = (const float*)d_in[4];
    float*       out     = (float*)d_out;

    prep_kernel<<<NBLK, 256>>>(doc_ids, D, O);
    score_kernel<<<BATCH / BPB, VD>>>(tnids, out);
}

// round 16
// speedup vs baseline: 1.2470x; 1.1787x over previous
#include <cuda_runtime.h>
#include <cuda_fp16.h>
#include <cstddef>

#define NW    100000
#define VD    128
#define BATCH 16384
#define KNUM  26
#define NPAIR 13   // k-pairs; warp wid owns p = wid + 4*i, i = 0..3
#define NPW   4

#define GB     512                 // gather blocks (256 thr, 8 warps x 4 b)
#define TW     32                  // w per transpose tile (full VD=128 in v)
#define TBXF   (NW / TW)           // 3125 transpose blocks
#define NBLK   (GB + TBXF)         // fused prep grid

// Scratch (static device globals; no allocation):
//   g_OTh: 25.6 MB fp16 transposed O, OTh[word][v]
//   g_dgh: 4 MB   fp16 gathered doc vectors, dgh[b][v]
__device__ __half g_OTh[(size_t)NW * VD];
__device__ __half g_dgh[(size_t)BATCH * VD];

// ---------------------------------------------------------------------------
// Kernel A (fused): blocks [0, GB) gather dgh[b] = fp16(D[doc_ids[b]]) with
// 4 b's per warp (MLP=4); blocks [GB, ...) transpose a FULL-V tile of O:
// 128 v x 32 w per block, so each of the 32 OTh rows is written in ONE
// contiguous 256B pass (8 threads x uint4). Reads stay coalesced float4.
// ---------------------------------------------------------------------------
__global__ __launch_bounds__(256)
void prep_kernel(const int* __restrict__ doc_ids,
                 const float* __restrict__ D,
                 const float* __restrict__ O) {
    const int t = threadIdx.x;

    if (blockIdx.x < GB) {
        // ---- gather partition ----
        const int warp = t >> 5;
        const int lane = t & 31;
        const int b0   = (blockIdx.x * 8 + warp) * 4;

        int doc[4];
#pragma unroll
        for (int i = 0; i < 4; i++) doc[i] = __ldg(&doc_ids[b0 + i]);

        float4 v[4];
#pragma unroll
        for (int i = 0; i < 4; i++) {
            v[i] = __ldg(reinterpret_cast<const float4*>(
                             D + (size_t)doc[i] * VD) + lane);
        }
#pragma unroll
        for (int i = 0; i < 4; i++) {
            const __half2 p0 = __floats2half2_rn(v[i].x, v[i].y);
            const __half2 p1 = __floats2half2_rn(v[i].z, v[i].w);
            uint2 o;
            o.x = *reinterpret_cast<const unsigned*>(&p0);
            o.y = *reinterpret_cast<const unsigned*>(&p1);
            *reinterpret_cast<uint2*>(
                g_dgh + (size_t)(b0 + i) * VD + 4 * lane) = o;
        }
        return;
    }

    // ---- transpose partition: tile = all 128 v x 32 w ----
    const int w0 = (blockIdx.x - GB) * TW;

    __shared__ float tile[VD][TW + 1];   // [v][w], +1 pad

    // read: 4 passes; thread (v = (t>>3)+32i, c = t&7) reads one float4
    // (w = 4c..4c+3). Per v-row: 8 threads x 16B = 128B coalesced.
    // smem store banks: (v + 4c + j) mod 32 -> conflict-free per j.
#pragma unroll
    for (int i = 0; i < 4; i++) {
        const int v = (t >> 3) + 32 * i;
        const int c = t & 7;
        const float4 f = __ldg(reinterpret_cast<const float4*>(
                                   O + (size_t)v * NW + w0) + c);
        tile[v][4 * c + 0] = f.x;
        tile[v][4 * c + 1] = f.y;
        tile[v][4 * c + 2] = f.z;
        tile[v][4 * c + 3] = f.w;
    }
    __syncthreads();

    // write: thread (w = t>>3, seg = t&7) converts v = 8seg..8seg+7 to
    // 4x half2 and writes one uint4. Per w-row: 8 threads x 16B = the full
    // 256B OTh row, perfectly contiguous.
    {
        const int w   = t >> 3;
        const int seg = t & 7;
        __half2 h[4];
#pragma unroll
        for (int j = 0; j < 4; j++) {
            h[j] = __floats2half2_rn(tile[8 * seg + 2 * j + 0][w],
                                     tile[8 * seg + 2 * j + 1][w]);
        }
        uint4 o;
        o.x = *reinterpret_cast<const unsigned*>(&h[0]);
        o.y = *reinterpret_cast<const unsigned*>(&h[1]);
        o.z = *reinterpret_cast<const unsigned*>(&h[2]);
        o.w = *reinterpret_cast<const unsigned*>(&h[3]);
        *reinterpret_cast<uint4*>(
            g_OTh + (size_t)(w0 + w) * VD + 8 * seg) = o;
    }
}

// ---------------------------------------------------------------------------
// Kernel B: score — EXACT R11 configuration (best measured: 15.9us).
// One block (128 thr = 4 warps) per b. Half-warp layout: lanes 0-15 own
// k=2p, lanes 16-31 own k=2p+1; each lane covers 8 v (uint4 = 4x half2).
// Warp wid owns pairs p = wid+4i (warp-uniform predication). Dot =
// HMUL2 + 3xHFMA2; 4 shuffles shared by two scores; loads batched (MLP=4).
// ---------------------------------------------------------------------------
__global__ __launch_bounds__(VD)
void score_kernel(const int* __restrict__ tnids,
                  float* __restrict__ out) {
    const int b    = blockIdx.x;
    const int t    = threadIdx.x;
    const int lane = t & 31;
    const int wid  = t >> 5;
    const int half = lane >> 4;   // 0: k=2p, 1: k=2p+1
    const int sub  = lane & 15;   // v = 8*sub .. 8*sub+7

    const uint4 dbits = __ldg(reinterpret_cast<const uint4*>(
                                  g_dgh + (size_t)b * VD + 8 * sub));
    const __half2 d0 = *reinterpret_cast<const __half2*>(&dbits.x);
    const __half2 d1 = *reinterpret_cast<const __half2*>(&dbits.y);
    const __half2 d2 = *reinterpret_cast<const __half2*>(&dbits.z);
    const __half2 d3 = *reinterpret_cast<const __half2*>(&dbits.w);

    int words[NPW];
#pragma unroll
    for (int i = 0; i < NPW; i++) {
        const int p = wid + 4 * i;
        words[i] = (p < NPAIR) ? __ldg(&tnids[b * KNUM + 2 * p + half]) : 0;
    }

    uint4 rows[NPW];
#pragma unroll
    for (int i = 0; i < NPW; i++) {
        const int p = wid + 4 * i;
        if (p < NPAIR) {
            rows[i] = __ldg(reinterpret_cast<const uint4*>(
                                g_OTh + (size_t)words[i] * VD + 8 * sub));
        }
    }

#pragma unroll
    for (int i = 0; i < NPW; i++) {
        const int p = wid + 4 * i;            // warp-uniform
        if (p < NPAIR) {
            const __half2 r0 = *reinterpret_cast<const __half2*>(&rows[i].x);
            const __half2 r1 = *reinterpret_cast<const __half2*>(&rows[i].y);
            const __half2 r2 = *reinterpret_cast<const __half2*>(&rows[i].z);
            const __half2 r3 = *reinterpret_cast<const __half2*>(&rows[i].w);
            __half2 acc = __hmul2(r0, d0);
            acc = __hfma2(r1, d1, acc);
            acc = __hfma2(r2, d2, acc);
            acc = __hfma2(r3, d3, acc);
            const float2 f = __half22float2(acc);
            float s = f.x + f.y;
            s += __shfl_xor_sync(0xffffffffu, s, 8);
            s += __shfl_xor_sync(0xffffffffu, s, 4);
            s += __shfl_xor_sync(0xffffffffu, s, 2);
            s += __shfl_xor_sync(0xffffffffu, s, 1);
            if (sub == 0) out[b * KNUM + 2 * p + half] = s;  // lanes 0, 16
        }
    }
}

// ---------------------------------------------------------------------------
// Inputs (metadata order): context_ids[B] i32 (unused), doc_ids[B] i32,
// target_noise_ids[B*K] i32, D[NUM_DOCS*VD] f32, O[VD*NW] f32.
// Output: out[B*K] f32.
// ---------------------------------------------------------------------------
extern "C" void kernel_launch(void* const* d_in, const int* in_sizes, int n_in,
                              void* d_out, int out_size) {
    const int*   doc_ids = (const int*)d_in[1];
    const int*   tnids   = (const int*)d_in[2];
    const float* D       = (const float*)d_in[3];
    const float* O       = (const float*)d_in[4];
    float*       out     = (float*)d_out;

    prep_kernel<<<NBLK, 256>>>(doc_ids, D, O);
    score_kernel<<<BATCH, VD>>>(tnids, out);
}

// round 17
// speedup vs baseline: 1.3282x; 1.0651x over previous
#include <cuda_runtime.h>
#include <cuda_fp16.h>
#include <cstddef>

#define NW    100000
#define VD    128
#define BATCH 16384
#define KNUM  26
#define NPAIR 13   // k-pairs; warp wid owns p = wid + 4*i, i = 0..3
#define NPW   4

#define GB     512                 // gather blocks (256 thr, 8 warps x 4 b)
#define TW     32                  // w per transpose tile (full VD=128 in v)
#define TBXF   (NW / TW)           // 3125 transpose blocks
#define NBLK   (GB + TBXF)         // fused prep grid

// Scratch (static device globals; no allocation):
//   g_OTh: 25.6 MB fp16 transposed O, OTh[word][v]
//   g_dgh: 4 MB   fp16 gathered doc vectors, dgh[b][v]
__device__ __half g_OTh[(size_t)NW * VD];
__device__ __half g_dgh[(size_t)BATCH * VD];

// ---------------------------------------------------------------------------
// Kernel A (fused): blocks [0, GB) gather dgh[b] = fp16(D[doc_ids[b]]) with
// 4 b's per warp (MLP=4); blocks [GB, ...) transpose a FULL-V tile of O:
// 128 v x 32 w per block; each of the 32 OTh rows written in ONE contiguous
// 256B pass. Ends with the PDL trigger so score can begin its ramp.
// ---------------------------------------------------------------------------
__global__ __launch_bounds__(256)
void prep_kernel(const int* __restrict__ doc_ids,
                 const float* __restrict__ D,
                 const float* __restrict__ O) {
    const int t = threadIdx.x;

    if (blockIdx.x < GB) {
        // ---- gather partition ----
        const int warp = t >> 5;
        const int lane = t & 31;
        const int b0   = (blockIdx.x * 8 + warp) * 4;

        int doc[4];
#pragma unroll
        for (int i = 0; i < 4; i++) doc[i] = __ldg(&doc_ids[b0 + i]);

        float4 v[4];
#pragma unroll
        for (int i = 0; i < 4; i++) {
            v[i] = __ldg(reinterpret_cast<const float4*>(
                             D + (size_t)doc[i] * VD) + lane);
        }
#pragma unroll
        for (int i = 0; i < 4; i++) {
            const __half2 p0 = __floats2half2_rn(v[i].x, v[i].y);
            const __half2 p1 = __floats2half2_rn(v[i].z, v[i].w);
            uint2 o;
            o.x = *reinterpret_cast<const unsigned*>(&p0);
            o.y = *reinterpret_cast<const unsigned*>(&p1);
            *reinterpret_cast<uint2*>(
                g_dgh + (size_t)(b0 + i) * VD + 4 * lane) = o;
        }
#if __CUDA_ARCH__ >= 900
        cudaTriggerProgrammaticLaunchCompletion();
#endif
        return;
    }

    // ---- transpose partition: tile = all 128 v x 32 w ----
    const int w0 = (blockIdx.x - GB) * TW;

    __shared__ float tile[VD][TW + 1];   // [v][w], +1 pad

#pragma unroll
    for (int i = 0; i < 4; i++) {
        const int v = (t >> 3) + 32 * i;
        const int c = t & 7;
        const float4 f = __ldg(reinterpret_cast<const float4*>(
                                   O + (size_t)v * NW + w0) + c);
        tile[v][4 * c + 0] = f.x;
        tile[v][4 * c + 1] = f.y;
        tile[v][4 * c + 2] = f.z;
        tile[v][4 * c + 3] = f.w;
    }
    __syncthreads();

    {
        const int w   = t >> 3;
        const int seg = t & 7;
        __half2 h[4];
#pragma unroll
        for (int j = 0; j < 4; j++) {
            h[j] = __floats2half2_rn(tile[8 * seg + 2 * j + 0][w],
                                     tile[8 * seg + 2 * j + 1][w]);
        }
        uint4 o;
        o.x = *reinterpret_cast<const unsigned*>(&h[0]);
        o.y = *reinterpret_cast<const unsigned*>(&h[1]);
        o.z = *reinterpret_cast<const unsigned*>(&h[2]);
        o.w = *reinterpret_cast<const unsigned*>(&h[3]);
        *reinterpret_cast<uint4*>(
            g_OTh + (size_t)(w0 + w) * VD + 8 * seg) = o;
    }
#if __CUDA_ARCH__ >= 900
    cudaTriggerProgrammaticLaunchCompletion();
#endif
}

// ---------------------------------------------------------------------------
// Kernel B: score — R11 body (best measured), PDL-overlapped with prep.
// Prep-independent prologue (word-id loads from tnids) runs BEFORE
// cudaGridDependencySynchronize(); g_dgh / g_OTh reads after it.
// ---------------------------------------------------------------------------
__global__ __launch_bounds__(VD)
void score_kernel(const int* __restrict__ tnids,
                  float* __restrict__ out) {
    const int b    = blockIdx.x;
    const int t    = threadIdx.x;
    const int lane = t & 31;
    const int wid  = t >> 5;
    const int half = lane >> 4;   // 0: k=2p, 1: k=2p+1
    const int sub  = lane & 15;   // v = 8*sub .. 8*sub+7

    // prologue: word ids (input-only, independent of prep)
    int words[NPW];
#pragma unroll
    for (int i = 0; i < NPW; i++) {
        const int p = wid + 4 * i;
        words[i] = (p < NPAIR) ? __ldg(&tnids[b * KNUM + 2 * p + half]) : 0;
    }

#if __CUDA_ARCH__ >= 900
    cudaGridDependencySynchronize();
#endif

    const uint4 dbits = __ldg(reinterpret_cast<const uint4*>(
                                  g_dgh + (size_t)b * VD + 8 * sub));
    const __half2 d0 = *reinterpret_cast<const __half2*>(&dbits.x);
    const __half2 d1 = *reinterpret_cast<const __half2*>(&dbits.y);
    const __half2 d2 = *reinterpret_cast<const __half2*>(&dbits.z);
    const __half2 d3 = *reinterpret_cast<const __half2*>(&dbits.w);

    uint4 rows[NPW];
#pragma unroll
    for (int i = 0; i < NPW; i++) {
        const int p = wid + 4 * i;
        if (p < NPAIR) {
            rows[i] = __ldg(reinterpret_cast<const uint4*>(
                                g_OTh + (size_t)words[i] * VD + 8 * sub));
        }
    }

#pragma unroll
    for (int i = 0; i < NPW; i++) {
        const int p = wid + 4 * i;            // warp-uniform
        if (p < NPAIR) {
            const __half2 r0 = *reinterpret_cast<const __half2*>(&rows[i].x);
            const __half2 r1 = *reinterpret_cast<const __half2*>(&rows[i].y);
            const __half2 r2 = *reinterpret_cast<const __half2*>(&rows[i].z);
            const __half2 r3 = *reinterpret_cast<const __half2*>(&rows[i].w);
            __half2 acc = __hmul2(r0, d0);
            acc = __hfma2(r1, d1, acc);
            acc = __hfma2(r2, d2, acc);
            acc = __hfma2(r3, d3, acc);
            const float2 f = __half22float2(acc);
            float s = f.x + f.y;
            s += __shfl_xor_sync(0xffffffffu, s, 8);
            s += __shfl_xor_sync(0xffffffffu, s, 4);
            s += __shfl_xor_sync(0xffffffffu, s, 2);
            s += __shfl_xor_sync(0xffffffffu, s, 1);
            if (sub == 0) out[b * KNUM + 2 * p + half] = s;  // lanes 0, 16
        }
    }
}

// ---------------------------------------------------------------------------
// Inputs (metadata order): context_ids[B] i32 (unused), doc_ids[B] i32,
// target_noise_ids[B*K] i32, D[NUM_DOCS*VD] f32, O[VD*NW] f32.
// Output: out[B*K] f32.
// ---------------------------------------------------------------------------
extern "C" void kernel_launch(void* const* d_in, const int* in_sizes, int n_in,
                              void* d_out, int out_size) {
    const int*   doc_ids = (const int*)d_in[1];
    const int*   tnids   = (const int*)d_in[2];
    const float* D       = (const float*)d_in[3];
    const float* O       = (const float*)d_in[4];
    float*       out     = (float*)d_out;

    prep_kernel<<<NBLK, 256>>>(doc_ids, D, O);

    // score with Programmatic Dependent Launch: overlaps prep's drain.
    cudaLaunchConfig_t cfg = {};
    cfg.gridDim  = dim3(BATCH, 1, 1);
    cfg.blockDim = dim3(VD, 1, 1);
    cudaLaunchAttribute attr[1];
    attr[0].id = cudaLaunchAttributeProgrammaticStreamSerialization;
    attr[0].val.programmaticStreamSerializationAllowed = 1;
    cfg.attrs    = attr;
    cfg.numAttrs = 1;
    cudaLaunchKernelEx(&cfg, score_kernel, tnids, (float*)d_out);
}